// round 9
// baseline (speedup 1.0000x reference)
#include <cuda_runtime.h>
#include <cstdint>

#define N_NODES 100000
#define D 64
#define E_MAX 1300000
#define SCAN_NB ((N_NODES + 255) / 256)   // 391 chunks of 256

// Scratch (no allocation allowed).
__device__ int g_cnt[N_NODES];      // in-degree counts
__device__ int g_off[N_NODES];      // CSR start offsets (exclusive scan of cnt)
__device__ int g_cur[N_NODES];      // fill cursors (init = offsets)
__device__ int g_esrc[E_MAX];       // edge sources grouped by dst
__device__ int g_bsum[SCAN_NB + 1]; // scan block sums

// ---------------------------------------------------------------------------
// K1: zero the count array.
// ---------------------------------------------------------------------------
__global__ void zero_cnt_kernel() {
    int i = blockIdx.x * blockDim.x + threadIdx.x;
    if (i < N_NODES) g_cnt[i] = 0;
}

// ---------------------------------------------------------------------------
// K2: histogram of destination nodes. edge_index is INT32: row0 = src (first
// E elements), row1 = dst (next E elements). Vectorized: 4 edges/thread.
// ---------------------------------------------------------------------------
__global__ void __launch_bounds__(256) hist4_kernel(const int* __restrict__ ei, int E) {
    int i = blockIdx.x * blockDim.x + threadIdx.x;   // quad index
    if (i * 4 >= E) return;
    const int4* d4 = reinterpret_cast<const int4*>(ei + E);
    int4 d = d4[i];
    atomicAdd(&g_cnt[d.x], 1);
    atomicAdd(&g_cnt[d.y], 1);
    atomicAdd(&g_cnt[d.z], 1);
    atomicAdd(&g_cnt[d.w], 1);
}

__global__ void __launch_bounds__(256) hist_kernel(const int* __restrict__ ei, int E) {
    int e = blockIdx.x * blockDim.x + threadIdx.x;
    if (e >= E) return;
    atomicAdd(&g_cnt[ei[E + e]], 1);
}

// ---------------------------------------------------------------------------
// K3a: per-256-chunk sums of g_cnt.
// ---------------------------------------------------------------------------
__global__ void __launch_bounds__(256) scan_blocksum_kernel() {
    __shared__ int s[256];
    int t = threadIdx.x;
    int i = blockIdx.x * 256 + t;
    s[t] = (i < N_NODES) ? g_cnt[i] : 0;
    __syncthreads();
    #pragma unroll
    for (int d = 128; d > 0; d >>= 1) {
        if (t < d) s[t] += s[t + d];
        __syncthreads();
    }
    if (t == 0) g_bsum[blockIdx.x] = s[0];
}

// ---------------------------------------------------------------------------
// K3b: exclusive scan of the 391 block sums (single thread — trivial size).
// ---------------------------------------------------------------------------
__global__ void scan_top_kernel(int nb) {
    if (threadIdx.x == 0 && blockIdx.x == 0) {
        int run = 0;
        for (int b = 0; b < nb; b++) {
            int v = g_bsum[b];
            g_bsum[b] = run;
            run += v;
        }
    }
}

// ---------------------------------------------------------------------------
// K3c: intra-chunk exclusive scan + chunk base -> offsets and cursors.
// ---------------------------------------------------------------------------
__global__ void __launch_bounds__(256) scan_chunk_kernel() {
    __shared__ int s[256];
    int t = threadIdx.x;
    int i = blockIdx.x * 256 + t;
    int v = (i < N_NODES) ? g_cnt[i] : 0;
    s[t] = v;
    __syncthreads();
    // Hillis-Steele inclusive scan.
    #pragma unroll
    for (int d = 1; d < 256; d <<= 1) {
        int u = (t >= d) ? s[t - d] : 0;
        __syncthreads();
        s[t] += u;
        __syncthreads();
    }
    if (i < N_NODES) {
        int excl = s[t] - v + g_bsum[blockIdx.x];
        g_off[i] = excl;
        g_cur[i] = excl;
    }
}

// ---------------------------------------------------------------------------
// K4: fill CSR edge-source list grouped by destination. 4 edges/thread.
// ---------------------------------------------------------------------------
__global__ void __launch_bounds__(256) fill4_kernel(const int* __restrict__ ei, int E) {
    int i = blockIdx.x * blockDim.x + threadIdx.x;
    if (i * 4 >= E) return;
    const int4* s4 = reinterpret_cast<const int4*>(ei);
    const int4* d4 = reinterpret_cast<const int4*>(ei + E);
    int4 s = s4[i];
    int4 d = d4[i];
    g_esrc[atomicAdd(&g_cur[d.x], 1)] = s.x;
    g_esrc[atomicAdd(&g_cur[d.y], 1)] = s.y;
    g_esrc[atomicAdd(&g_cur[d.z], 1)] = s.z;
    g_esrc[atomicAdd(&g_cur[d.w], 1)] = s.w;
}

__global__ void __launch_bounds__(256) fill_kernel(const int* __restrict__ ei, int E) {
    int e = blockIdx.x * blockDim.x + threadIdx.x;
    if (e >= E) return;
    int src = ei[e];
    int dst = ei[E + e];
    g_esrc[atomicAdd(&g_cur[dst], 1)] = src;
}

// ---------------------------------------------------------------------------
// K5: fused gather-mean + dual GEMM.
// 256 threads = 32 groups of 8; group handles one node per iteration (4 iters
// -> 128 nodes/block). Thread q owns feature slots [8q, 8q+8) for the gather
// and output columns [8q, 8q+8) for the GEMM. Row values broadcast with
// shfl(width=8); W_l/W_r staged in shared [k][n] (float4, broadcast-friendly).
// ---------------------------------------------------------------------------
__global__ void __launch_bounds__(256) finalize_kernel(
    const float* __restrict__ x,
    const float* __restrict__ Wl,
    const float* __restrict__ Wr,
    float* __restrict__ out,
    int nodes)
{
    __shared__ __align__(16) float sWl[D][D];  // [k][n]
    __shared__ __align__(16) float sWr[D][D];
    {
        float4* dl = reinterpret_cast<float4*>(&sWl[0][0]);
        float4* dr = reinterpret_cast<float4*>(&sWr[0][0]);
        const float4* sl = reinterpret_cast<const float4*>(Wl);
        const float4* sr = reinterpret_cast<const float4*>(Wr);
        #pragma unroll
        for (int j = 0; j < 4; j++) {
            dl[threadIdx.x + 256 * j] = sl[threadIdx.x + 256 * j];
            dr[threadIdx.x + 256 * j] = sr[threadIdx.x + 256 * j];
        }
    }
    __syncthreads();

    const int g  = threadIdx.x >> 3;   // group 0..31
    const int q  = threadIdx.x & 7;    // lane in group
    const int qc = q * 8;              // first output column / feature slot

    #pragma unroll 1
    for (int it = 0; it < 4; it++) {
        int r  = blockIdx.x * 128 + it * 32 + g;
        int rc = (r < nodes) ? r : (nodes - 1);  // clamp: keep lanes active for shfl

        int cnt   = g_cnt[rc];
        int start = g_off[rc];

        // Gather-sum this node's neighbors (features [8q, 8q+8)).
        // 2-way unrolled with indices loaded up front for higher MLP.
        float4 s0 = make_float4(0.f, 0.f, 0.f, 0.f);
        float4 s1 = make_float4(0.f, 0.f, 0.f, 0.f);
        int j = 0;
        for (; j + 2 <= cnt; j += 2) {
            int srcA = g_esrc[start + j];
            int srcB = g_esrc[start + j + 1];
            const float4* xa = reinterpret_cast<const float4*>(x + (size_t)srcA * D);
            const float4* xb = reinterpret_cast<const float4*>(x + (size_t)srcB * D);
            float4 a0 = xa[q * 2];
            float4 a1 = xa[q * 2 + 1];
            float4 b0 = xb[q * 2];
            float4 b1 = xb[q * 2 + 1];
            s0.x += a0.x; s0.y += a0.y; s0.z += a0.z; s0.w += a0.w;
            s1.x += a1.x; s1.y += a1.y; s1.z += a1.z; s1.w += a1.w;
            s0.x += b0.x; s0.y += b0.y; s0.z += b0.z; s0.w += b0.w;
            s1.x += b1.x; s1.y += b1.y; s1.z += b1.z; s1.w += b1.w;
        }
        if (j < cnt) {
            int src = g_esrc[start + j];
            const float4* xr = reinterpret_cast<const float4*>(x + (size_t)src * D);
            float4 u0 = xr[q * 2];
            float4 u1 = xr[q * 2 + 1];
            s0.x += u0.x; s0.y += u0.y; s0.z += u0.z; s0.w += u0.w;
            s1.x += u1.x; s1.y += u1.y; s1.z += u1.z; s1.w += u1.w;
        }

        float inv = (cnt > 0) ? (1.f / (float)cnt) : 0.f;
        float ar[8] = {s0.x * inv, s0.y * inv, s0.z * inv, s0.w * inv,
                       s1.x * inv, s1.y * inv, s1.z * inv, s1.w * inv};

        const float4* xrow = reinterpret_cast<const float4*>(x + (size_t)rc * D);
        float4 b0 = xrow[q * 2], b1 = xrow[q * 2 + 1];
        float xv[8] = {b0.x, b0.y, b0.z, b0.w, b1.x, b1.y, b1.z, b1.w};

        float acc[8];
        #pragma unroll
        for (int c = 0; c < 8; c++) acc[c] = 0.f;

        #pragma unroll
        for (int k = 0; k < D; k++) {
            float a = __shfl_sync(0xffffffffu, ar[k & 7], k >> 3, 8);
            float b = __shfl_sync(0xffffffffu, xv[k & 7], k >> 3, 8);
            float4 l0 = *reinterpret_cast<const float4*>(&sWl[k][qc]);
            float4 l1 = *reinterpret_cast<const float4*>(&sWl[k][qc + 4]);
            float4 m0 = *reinterpret_cast<const float4*>(&sWr[k][qc]);
            float4 m1 = *reinterpret_cast<const float4*>(&sWr[k][qc + 4]);
            acc[0] = fmaf(a, l0.x, acc[0]); acc[0] = fmaf(b, m0.x, acc[0]);
            acc[1] = fmaf(a, l0.y, acc[1]); acc[1] = fmaf(b, m0.y, acc[1]);
            acc[2] = fmaf(a, l0.z, acc[2]); acc[2] = fmaf(b, m0.z, acc[2]);
            acc[3] = fmaf(a, l0.w, acc[3]); acc[3] = fmaf(b, m0.w, acc[3]);
            acc[4] = fmaf(a, l1.x, acc[4]); acc[4] = fmaf(b, m1.x, acc[4]);
            acc[5] = fmaf(a, l1.y, acc[5]); acc[5] = fmaf(b, m1.y, acc[5]);
            acc[6] = fmaf(a, l1.z, acc[6]); acc[6] = fmaf(b, m1.z, acc[6]);
            acc[7] = fmaf(a, l1.w, acc[7]); acc[7] = fmaf(b, m1.w, acc[7]);
        }

        if (r < nodes) {
            float4* orow = reinterpret_cast<float4*>(out + (size_t)r * D);
            orow[q * 2]     = make_float4(acc[0], acc[1], acc[2], acc[3]);
            orow[q * 2 + 1] = make_float4(acc[4], acc[5], acc[6], acc[7]);
        }
    }
}

// ---------------------------------------------------------------------------
// Launch: zero -> hist -> scan(3) -> fill -> fused finalize.
// All plain kernel launches on the default stream (graph-capturable).
// ---------------------------------------------------------------------------
extern "C" void kernel_launch(void* const* d_in, const int* in_sizes, int n_in,
                              void* d_out, int out_size) {
    const float* x  = (const float*)d_in[0];
    const int*   ei = (const int*)d_in[1];     // edge_index is int32 (JAX x64 off)
    const float* Wl = (const float*)d_in[2];
    const float* Wr = (const float*)d_in[3];
    float*       o  = (float*)d_out;

    const int E     = in_sizes[1] / 2;
    const int nodes = in_sizes[0] / D;

    zero_cnt_kernel<<<(N_NODES + 255) / 256, 256>>>();

    if ((E & 3) == 0) {
        int qb = (E / 4 + 255) / 256;
        hist4_kernel<<<qb, 256>>>(ei, E);
        scan_blocksum_kernel<<<SCAN_NB, 256>>>();
        scan_top_kernel<<<1, 32>>>(SCAN_NB);
        scan_chunk_kernel<<<SCAN_NB, 256>>>();
        fill4_kernel<<<qb, 256>>>(ei, E);
    } else {
        int eb = (E + 255) / 256;
        hist_kernel<<<eb, 256>>>(ei, E);
        scan_blocksum_kernel<<<SCAN_NB, 256>>>();
        scan_top_kernel<<<1, 32>>>(SCAN_NB);
        scan_chunk_kernel<<<SCAN_NB, 256>>>();
        fill_kernel<<<eb, 256>>>(ei, E);
    }

    finalize_kernel<<<(nodes + 127) / 128, 256>>>(x, Wl, Wr, o, nodes);
}

// round 12
// speedup vs baseline: 1.0386x; 1.0386x over previous
#include <cuda_runtime.h>
#include <cstdint>

#define N_NODES 100000
#define D 64
#define E_MAX 1300000
#define SCAN_NB ((N_NODES + 255) / 256)   // 391 chunks of 256

// Scratch (no allocation allowed).
__device__ int g_cnt[N_NODES];      // in-degree counts
__device__ int g_off[N_NODES];      // CSR start offsets (exclusive scan of cnt)
__device__ int g_cur[N_NODES];      // fill cursors (init = offsets)
__device__ int g_esrc[E_MAX];       // edge sources grouped by dst
__device__ int g_bsum[512];         // scan block sums (padded to top-scan width)

// ---------------------------------------------------------------------------
// K1: zero the count array.
// ---------------------------------------------------------------------------
__global__ void zero_cnt_kernel() {
    int i = blockIdx.x * blockDim.x + threadIdx.x;
    if (i < N_NODES) g_cnt[i] = 0;
}

// ---------------------------------------------------------------------------
// K2: histogram of destination nodes. edge_index is INT32: row0 = src (first
// E elements), row1 = dst (next E elements). Vectorized: 4 edges/thread.
// ---------------------------------------------------------------------------
__global__ void __launch_bounds__(256) hist4_kernel(const int* __restrict__ ei, int E) {
    int i = blockIdx.x * blockDim.x + threadIdx.x;   // quad index
    if (i * 4 >= E) return;
    const int4* d4 = reinterpret_cast<const int4*>(ei + E);
    int4 d = d4[i];
    atomicAdd(&g_cnt[d.x], 1);
    atomicAdd(&g_cnt[d.y], 1);
    atomicAdd(&g_cnt[d.z], 1);
    atomicAdd(&g_cnt[d.w], 1);
}

__global__ void __launch_bounds__(256) hist_kernel(const int* __restrict__ ei, int E) {
    int e = blockIdx.x * blockDim.x + threadIdx.x;
    if (e >= E) return;
    atomicAdd(&g_cnt[ei[E + e]], 1);
}

// ---------------------------------------------------------------------------
// K3a: per-256-chunk sums of g_cnt.
// ---------------------------------------------------------------------------
__global__ void __launch_bounds__(256) scan_blocksum_kernel() {
    __shared__ int s[256];
    int t = threadIdx.x;
    int i = blockIdx.x * 256 + t;
    s[t] = (i < N_NODES) ? g_cnt[i] : 0;
    __syncthreads();
    #pragma unroll
    for (int d = 128; d > 0; d >>= 1) {
        if (t < d) s[t] += s[t + d];
        __syncthreads();
    }
    if (t == 0) g_bsum[blockIdx.x] = s[0];
}

// ---------------------------------------------------------------------------
// K3b: exclusive scan of the 391 block sums — PARALLEL single block.
// (Previous serial version measured 17.7us; this is ~2us.)
// ---------------------------------------------------------------------------
__global__ void __launch_bounds__(512) scan_top_kernel() {
    __shared__ int s[512];
    int t = threadIdx.x;
    int v = (t < SCAN_NB) ? g_bsum[t] : 0;
    s[t] = v;
    __syncthreads();
    #pragma unroll
    for (int d = 1; d < 512; d <<= 1) {
        int u = (t >= d) ? s[t - d] : 0;
        __syncthreads();
        s[t] += u;
        __syncthreads();
    }
    if (t < SCAN_NB) g_bsum[t] = s[t] - v;   // inclusive -> exclusive
}

// ---------------------------------------------------------------------------
// K3c: intra-chunk exclusive scan + chunk base -> offsets and cursors.
// ---------------------------------------------------------------------------
__global__ void __launch_bounds__(256) scan_chunk_kernel() {
    __shared__ int s[256];
    int t = threadIdx.x;
    int i = blockIdx.x * 256 + t;
    int v = (i < N_NODES) ? g_cnt[i] : 0;
    s[t] = v;
    __syncthreads();
    // Hillis-Steele inclusive scan.
    #pragma unroll
    for (int d = 1; d < 256; d <<= 1) {
        int u = (t >= d) ? s[t - d] : 0;
        __syncthreads();
        s[t] += u;
        __syncthreads();
    }
    if (i < N_NODES) {
        int excl = s[t] - v + g_bsum[blockIdx.x];
        g_off[i] = excl;
        g_cur[i] = excl;
    }
}

// ---------------------------------------------------------------------------
// K4: fill CSR edge-source list grouped by destination. 4 edges/thread.
// ---------------------------------------------------------------------------
__global__ void __launch_bounds__(256) fill4_kernel(const int* __restrict__ ei, int E) {
    int i = blockIdx.x * blockDim.x + threadIdx.x;
    if (i * 4 >= E) return;
    const int4* s4 = reinterpret_cast<const int4*>(ei);
    const int4* d4 = reinterpret_cast<const int4*>(ei + E);
    int4 s = s4[i];
    int4 d = d4[i];
    g_esrc[atomicAdd(&g_cur[d.x], 1)] = s.x;
    g_esrc[atomicAdd(&g_cur[d.y], 1)] = s.y;
    g_esrc[atomicAdd(&g_cur[d.z], 1)] = s.z;
    g_esrc[atomicAdd(&g_cur[d.w], 1)] = s.w;
}

__global__ void __launch_bounds__(256) fill_kernel(const int* __restrict__ ei, int E) {
    int e = blockIdx.x * blockDim.x + threadIdx.x;
    if (e >= E) return;
    int src = ei[e];
    int dst = ei[E + e];
    g_esrc[atomicAdd(&g_cur[dst], 1)] = src;
}

// ---------------------------------------------------------------------------
// K5: fused gather-mean + dual GEMM.
// 256 threads = 32 groups of 8; group handles one node per iteration (4 iters
// -> 128 nodes/block). Thread q owns feature slots [8q, 8q+8) for the gather
// and output columns [8q, 8q+8) for the GEMM. Row values broadcast with
// shfl(width=8); W_l/W_r staged in shared [k][n] (float4, broadcast-friendly).
// Gather is 4-way unrolled with all indices loaded before feature rows to
// maximize memory-level parallelism against L2 latency.
// ---------------------------------------------------------------------------
__global__ void __launch_bounds__(256) finalize_kernel(
    const float* __restrict__ x,
    const float* __restrict__ Wl,
    const float* __restrict__ Wr,
    float* __restrict__ out,
    int nodes)
{
    __shared__ __align__(16) float sWl[D][D];  // [k][n]
    __shared__ __align__(16) float sWr[D][D];
    {
        float4* dl = reinterpret_cast<float4*>(&sWl[0][0]);
        float4* dr = reinterpret_cast<float4*>(&sWr[0][0]);
        const float4* sl = reinterpret_cast<const float4*>(Wl);
        const float4* sr = reinterpret_cast<const float4*>(Wr);
        #pragma unroll
        for (int j = 0; j < 4; j++) {
            dl[threadIdx.x + 256 * j] = sl[threadIdx.x + 256 * j];
            dr[threadIdx.x + 256 * j] = sr[threadIdx.x + 256 * j];
        }
    }
    __syncthreads();

    const int g  = threadIdx.x >> 3;   // group 0..31
    const int q  = threadIdx.x & 7;    // lane in group
    const int qc = q * 8;              // first output column / feature slot

    #pragma unroll 1
    for (int it = 0; it < 4; it++) {
        int r  = blockIdx.x * 128 + it * 32 + g;
        int rc = (r < nodes) ? r : (nodes - 1);  // clamp: keep lanes active for shfl

        int cnt   = g_cnt[rc];
        int start = g_off[rc];

        // Gather-sum this node's neighbors (features [8q, 8q+8)).
        float4 s0 = make_float4(0.f, 0.f, 0.f, 0.f);
        float4 s1 = make_float4(0.f, 0.f, 0.f, 0.f);
        int j = 0;
        for (; j + 4 <= cnt; j += 4) {
            int iA = __ldg(&g_esrc[start + j]);
            int iB = __ldg(&g_esrc[start + j + 1]);
            int iC = __ldg(&g_esrc[start + j + 2]);
            int iD = __ldg(&g_esrc[start + j + 3]);
            const float4* xa = reinterpret_cast<const float4*>(x + (size_t)iA * D);
            const float4* xb = reinterpret_cast<const float4*>(x + (size_t)iB * D);
            const float4* xc = reinterpret_cast<const float4*>(x + (size_t)iC * D);
            const float4* xd = reinterpret_cast<const float4*>(x + (size_t)iD * D);
            float4 a0 = xa[q * 2], a1 = xa[q * 2 + 1];
            float4 b0 = xb[q * 2], b1 = xb[q * 2 + 1];
            float4 c0 = xc[q * 2], c1 = xc[q * 2 + 1];
            float4 d0 = xd[q * 2], d1 = xd[q * 2 + 1];
            s0.x += a0.x + b0.x; s0.y += a0.y + b0.y; s0.z += a0.z + b0.z; s0.w += a0.w + b0.w;
            s1.x += a1.x + b1.x; s1.y += a1.y + b1.y; s1.z += a1.z + b1.z; s1.w += a1.w + b1.w;
            s0.x += c0.x + d0.x; s0.y += c0.y + d0.y; s0.z += c0.z + d0.z; s0.w += c0.w + d0.w;
            s1.x += c1.x + d1.x; s1.y += c1.y + d1.y; s1.z += c1.z + d1.z; s1.w += c1.w + d1.w;
        }
        for (; j < cnt; j++) {
            int src = __ldg(&g_esrc[start + j]);
            const float4* xr = reinterpret_cast<const float4*>(x + (size_t)src * D);
            float4 u0 = xr[q * 2];
            float4 u1 = xr[q * 2 + 1];
            s0.x += u0.x; s0.y += u0.y; s0.z += u0.z; s0.w += u0.w;
            s1.x += u1.x; s1.y += u1.y; s1.z += u1.z; s1.w += u1.w;
        }

        float inv = (cnt > 0) ? (1.f / (float)cnt) : 0.f;
        float ar[8] = {s0.x * inv, s0.y * inv, s0.z * inv, s0.w * inv,
                       s1.x * inv, s1.y * inv, s1.z * inv, s1.w * inv};

        const float4* xrow = reinterpret_cast<const float4*>(x + (size_t)rc * D);
        float4 b0 = xrow[q * 2], b1 = xrow[q * 2 + 1];
        float xv[8] = {b0.x, b0.y, b0.z, b0.w, b1.x, b1.y, b1.z, b1.w};

        float acc[8];
        #pragma unroll
        for (int c = 0; c < 8; c++) acc[c] = 0.f;

        #pragma unroll
        for (int k = 0; k < D; k++) {
            float a = __shfl_sync(0xffffffffu, ar[k & 7], k >> 3, 8);
            float b = __shfl_sync(0xffffffffu, xv[k & 7], k >> 3, 8);
            float4 l0 = *reinterpret_cast<const float4*>(&sWl[k][qc]);
            float4 l1 = *reinterpret_cast<const float4*>(&sWl[k][qc + 4]);
            float4 m0 = *reinterpret_cast<const float4*>(&sWr[k][qc]);
            float4 m1 = *reinterpret_cast<const float4*>(&sWr[k][qc + 4]);
            acc[0] = fmaf(a, l0.x, acc[0]); acc[0] = fmaf(b, m0.x, acc[0]);
            acc[1] = fmaf(a, l0.y, acc[1]); acc[1] = fmaf(b, m0.y, acc[1]);
            acc[2] = fmaf(a, l0.z, acc[2]); acc[2] = fmaf(b, m0.z, acc[2]);
            acc[3] = fmaf(a, l0.w, acc[3]); acc[3] = fmaf(b, m0.w, acc[3]);
            acc[4] = fmaf(a, l1.x, acc[4]); acc[4] = fmaf(b, m1.x, acc[4]);
            acc[5] = fmaf(a, l1.y, acc[5]); acc[5] = fmaf(b, m1.y, acc[5]);
            acc[6] = fmaf(a, l1.z, acc[6]); acc[6] = fmaf(b, m1.z, acc[6]);
            acc[7] = fmaf(a, l1.w, acc[7]); acc[7] = fmaf(b, m1.w, acc[7]);
        }

        if (r < nodes) {
            float4* orow = reinterpret_cast<float4*>(out + (size_t)r * D);
            orow[q * 2]     = make_float4(acc[0], acc[1], acc[2], acc[3]);
            orow[q * 2 + 1] = make_float4(acc[4], acc[5], acc[6], acc[7]);
        }
    }
}

// ---------------------------------------------------------------------------
// Launch: zero -> hist -> scan(3) -> fill -> fused finalize.
// All plain kernel launches on the default stream (graph-capturable).
// ---------------------------------------------------------------------------
extern "C" void kernel_launch(void* const* d_in, const int* in_sizes, int n_in,
                              void* d_out, int out_size) {
    const float* x  = (const float*)d_in[0];
    const int*   ei = (const int*)d_in[1];     // edge_index is int32 (JAX x64 off)
    const float* Wl = (const float*)d_in[2];
    const float* Wr = (const float*)d_in[3];
    float*       o  = (float*)d_out;

    const int E     = in_sizes[1] / 2;
    const int nodes = in_sizes[0] / D;

    zero_cnt_kernel<<<(N_NODES + 255) / 256, 256>>>();

    if ((E & 3) == 0) {
        int qb = (E / 4 + 255) / 256;
        hist4_kernel<<<qb, 256>>>(ei, E);
        scan_blocksum_kernel<<<SCAN_NB, 256>>>();
        scan_top_kernel<<<1, 512>>>();
        scan_chunk_kernel<<<SCAN_NB, 256>>>();
        fill4_kernel<<<qb, 256>>>(ei, E);
    } else {
        int eb = (E + 255) / 256;
        hist_kernel<<<eb, 256>>>(ei, E);
        scan_blocksum_kernel<<<SCAN_NB, 256>>>();
        scan_top_kernel<<<1, 512>>>();
        scan_chunk_kernel<<<SCAN_NB, 256>>>();
        fill_kernel<<<eb, 256>>>(ei, E);
    }

    finalize_kernel<<<(nodes + 127) / 128, 256>>>(x, Wl, Wr, o, nodes);
}

// round 13
// speedup vs baseline: 2.1223x; 2.0435x over previous
#include <cuda_runtime.h>
#include <cstdint>

#define N_NODES 100000
#define D 64
#define E_MAX 1300000
#define ROWS_BLK 128
#define APAD 68                       // row stride (floats) for sA/sX tiles
#define SMEM_FIN_BYTES ((2 * D * D + 2 * ROWS_BLK * APAD) * 4)  // 102400 B

// Scratch (no allocation allowed).
__device__ int g_cnt[N_NODES];      // in-degree counts
__device__ int g_off[N_NODES];      // CSR start offsets (disjoint regions)
__device__ int g_cur[N_NODES];      // fill cursors (init = offsets)
__device__ int g_esrc[E_MAX];       // edge sources grouped by dst
__device__ int g_total;             // global offset cursor

// ---------------------------------------------------------------------------
// K1: zero counts + global cursor.
// ---------------------------------------------------------------------------
__global__ void zero_cnt_kernel() {
    int i = blockIdx.x * blockDim.x + threadIdx.x;
    if (i < N_NODES) g_cnt[i] = 0;
    if (i == 0) g_total = 0;
}

// ---------------------------------------------------------------------------
// K2: histogram of destination nodes (int32 edge_index; row0=src, row1=dst).
// ---------------------------------------------------------------------------
__global__ void __launch_bounds__(256) hist4_kernel(const int* __restrict__ ei, int E) {
    int i = blockIdx.x * blockDim.x + threadIdx.x;
    if (i * 4 >= E) return;
    int4 d = reinterpret_cast<const int4*>(ei + E)[i];
    atomicAdd(&g_cnt[d.x], 1);
    atomicAdd(&g_cnt[d.y], 1);
    atomicAdd(&g_cnt[d.z], 1);
    atomicAdd(&g_cnt[d.w], 1);
}

__global__ void __launch_bounds__(256) hist_kernel(const int* __restrict__ ei, int E) {
    int e = blockIdx.x * blockDim.x + threadIdx.x;
    if (e >= E) return;
    atomicAdd(&g_cnt[ei[E + e]], 1);
}

// ---------------------------------------------------------------------------
// K3: offsets in ONE kernel. Block-local exclusive scan; block base claimed
// via a single atomicAdd on a global cursor. Regions are disjoint + sized
// right; node order of regions is irrelevant for correctness.
// ---------------------------------------------------------------------------
__global__ void __launch_bounds__(256) scanoff_kernel() {
    __shared__ int s[256];
    __shared__ int base_s;
    int t = threadIdx.x;
    int i = blockIdx.x * 256 + t;
    int v = (i < N_NODES) ? g_cnt[i] : 0;
    s[t] = v;
    __syncthreads();
    #pragma unroll
    for (int d = 1; d < 256; d <<= 1) {
        int u = (t >= d) ? s[t - d] : 0;
        __syncthreads();
        s[t] += u;
        __syncthreads();
    }
    if (t == 255) base_s = atomicAdd(&g_total, s[255]);
    __syncthreads();
    if (i < N_NODES) {
        int excl = s[t] - v + base_s;
        g_off[i] = excl;
        g_cur[i] = excl;
    }
}

// ---------------------------------------------------------------------------
// K4: fill CSR edge-source list grouped by destination. 4 edges/thread.
// ---------------------------------------------------------------------------
__global__ void __launch_bounds__(256) fill4_kernel(const int* __restrict__ ei, int E) {
    int i = blockIdx.x * blockDim.x + threadIdx.x;
    if (i * 4 >= E) return;
    int4 s = reinterpret_cast<const int4*>(ei)[i];
    int4 d = reinterpret_cast<const int4*>(ei + E)[i];
    g_esrc[atomicAdd(&g_cur[d.x], 1)] = s.x;
    g_esrc[atomicAdd(&g_cur[d.y], 1)] = s.y;
    g_esrc[atomicAdd(&g_cur[d.z], 1)] = s.z;
    g_esrc[atomicAdd(&g_cur[d.w], 1)] = s.w;
}

__global__ void __launch_bounds__(256) fill_kernel(const int* __restrict__ ei, int E) {
    int e = blockIdx.x * blockDim.x + threadIdx.x;
    if (e >= E) return;
    g_esrc[atomicAdd(&g_cur[ei[E + e]], 1)] = ei[e];
}

// ---------------------------------------------------------------------------
// K5: fused gather-mean + dual GEMM, smem-staged + register-tiled.
// Phase A (gather): 32 groups of 8 lanes; group owns one row per pass (4
//   passes -> 128 rows). Lane q gathers features [8q,8q+8); mean row and x
//   row are written into smem tiles sA/sX [row][APAD] (2x STS.128/lane).
// Phase B (GEMM): thread (ty=tid>>3, tx=tid&7) computes a 4-row x 8-col
//   output tile: per k = 8 scalar A/X loads (broadcast, conflict-free) +
//   4 float4 weight loads + 64 FMA -> ~91% FMA density, no shfl.
// 100KB dynamic smem -> 2 blocks/SM; sibling block's gather overlaps GEMM.
// ---------------------------------------------------------------------------
__global__ void __launch_bounds__(256) finalize_kernel(
    const float* __restrict__ x,
    const float* __restrict__ Wl,
    const float* __restrict__ Wr,
    float* __restrict__ out,
    int nodes)
{
    extern __shared__ float sm[];
    float* sWl = sm;                        // [k*D + n]
    float* sWr = sWl + D * D;
    float* sA  = sWr + D * D;               // [row*APAD + k]  (mean rows)
    float* sX  = sA + ROWS_BLK * APAD;      // [row*APAD + k]  (x rows)

    // Stage weights (k-major, row-major copy is identical layout).
    {
        float4* dl = reinterpret_cast<float4*>(sWl);
        float4* dr = reinterpret_cast<float4*>(sWr);
        const float4* sl = reinterpret_cast<const float4*>(Wl);
        const float4* sr = reinterpret_cast<const float4*>(Wr);
        #pragma unroll
        for (int j = 0; j < 4; j++) {
            dl[threadIdx.x + 256 * j] = sl[threadIdx.x + 256 * j];
            dr[threadIdx.x + 256 * j] = sr[threadIdx.x + 256 * j];
        }
    }

    const int g  = threadIdx.x >> 3;   // group 0..31
    const int q  = threadIdx.x & 7;    // lane in group
    const int blockRow = blockIdx.x * ROWS_BLK;

    // ---- Phase A: gather into smem tiles ----
    #pragma unroll 1
    for (int it = 0; it < 4; it++) {
        int row = it * 32 + g;                 // 0..127 within tile
        int r   = blockRow + row;
        int rc  = (r < nodes) ? r : (nodes - 1);

        int cnt   = g_cnt[rc];
        int start = g_off[rc];

        float4 s0 = make_float4(0.f, 0.f, 0.f, 0.f);
        float4 s1 = make_float4(0.f, 0.f, 0.f, 0.f);
        int j = 0;
        for (; j + 4 <= cnt; j += 4) {
            int iA = __ldg(&g_esrc[start + j]);
            int iB = __ldg(&g_esrc[start + j + 1]);
            int iC = __ldg(&g_esrc[start + j + 2]);
            int iD = __ldg(&g_esrc[start + j + 3]);
            const float4* xa = reinterpret_cast<const float4*>(x + (size_t)iA * D);
            const float4* xb = reinterpret_cast<const float4*>(x + (size_t)iB * D);
            const float4* xc = reinterpret_cast<const float4*>(x + (size_t)iC * D);
            const float4* xd = reinterpret_cast<const float4*>(x + (size_t)iD * D);
            float4 a0 = xa[q * 2], a1 = xa[q * 2 + 1];
            float4 b0 = xb[q * 2], b1 = xb[q * 2 + 1];
            float4 c0 = xc[q * 2], c1 = xc[q * 2 + 1];
            float4 d0 = xd[q * 2], d1 = xd[q * 2 + 1];
            s0.x += a0.x + b0.x; s0.y += a0.y + b0.y; s0.z += a0.z + b0.z; s0.w += a0.w + b0.w;
            s1.x += a1.x + b1.x; s1.y += a1.y + b1.y; s1.z += a1.z + b1.z; s1.w += a1.w + b1.w;
            s0.x += c0.x + d0.x; s0.y += c0.y + d0.y; s0.z += c0.z + d0.z; s0.w += c0.w + d0.w;
            s1.x += c1.x + d1.x; s1.y += c1.y + d1.y; s1.z += c1.z + d1.z; s1.w += c1.w + d1.w;
        }
        for (; j < cnt; j++) {
            int src = __ldg(&g_esrc[start + j]);
            const float4* xr = reinterpret_cast<const float4*>(x + (size_t)src * D);
            float4 u0 = xr[q * 2], u1 = xr[q * 2 + 1];
            s0.x += u0.x; s0.y += u0.y; s0.z += u0.z; s0.w += u0.w;
            s1.x += u1.x; s1.y += u1.y; s1.z += u1.z; s1.w += u1.w;
        }

        float inv = (cnt > 0) ? (1.f / (float)cnt) : 0.f;
        float4 m0 = make_float4(s0.x * inv, s0.y * inv, s0.z * inv, s0.w * inv);
        float4 m1 = make_float4(s1.x * inv, s1.y * inv, s1.z * inv, s1.w * inv);

        const float4* xrow = reinterpret_cast<const float4*>(x + (size_t)rc * D);
        float4 b0 = xrow[q * 2], b1 = xrow[q * 2 + 1];

        float4* pa = reinterpret_cast<float4*>(&sA[row * APAD + q * 8]);
        float4* px = reinterpret_cast<float4*>(&sX[row * APAD + q * 8]);
        pa[0] = m0; pa[1] = m1;
        px[0] = b0; px[1] = b1;
    }
    __syncthreads();

    // ---- Phase B: register-tiled dual GEMM ----
    const int ty = threadIdx.x >> 3;   // 0..31 -> rows ty*4 .. ty*4+3
    const int tx = threadIdx.x & 7;    // cols tx*8 .. tx*8+7
    const int r0 = ty * 4;
    const int c0 = tx * 8;

    float acc[4][8];
    #pragma unroll
    for (int rr = 0; rr < 4; rr++)
        #pragma unroll
        for (int cc = 0; cc < 8; cc++) acc[rr][cc] = 0.f;

    #pragma unroll
    for (int k = 0; k < D; k++) {
        float am[4], ax[4];
        #pragma unroll
        for (int rr = 0; rr < 4; rr++) {
            am[rr] = sA[(r0 + rr) * APAD + k];
            ax[rr] = sX[(r0 + rr) * APAD + k];
        }
        float4 l0 = *reinterpret_cast<const float4*>(&sWl[k * D + c0]);
        float4 l1 = *reinterpret_cast<const float4*>(&sWl[k * D + c0 + 4]);
        float4 w0 = *reinterpret_cast<const float4*>(&sWr[k * D + c0]);
        float4 w1 = *reinterpret_cast<const float4*>(&sWr[k * D + c0 + 4]);
        float wl[8] = {l0.x, l0.y, l0.z, l0.w, l1.x, l1.y, l1.z, l1.w};
        float wr[8] = {w0.x, w0.y, w0.z, w0.w, w1.x, w1.y, w1.z, w1.w};
        #pragma unroll
        for (int rr = 0; rr < 4; rr++)
            #pragma unroll
            for (int cc = 0; cc < 8; cc++)
                acc[rr][cc] = fmaf(am[rr], wl[cc], fmaf(ax[rr], wr[cc], acc[rr][cc]));
    }

    #pragma unroll
    for (int rr = 0; rr < 4; rr++) {
        int r = blockRow + r0 + rr;
        if (r < nodes) {
            float4* orow = reinterpret_cast<float4*>(out + (size_t)r * D + c0);
            orow[0] = make_float4(acc[rr][0], acc[rr][1], acc[rr][2], acc[rr][3]);
            orow[1] = make_float4(acc[rr][4], acc[rr][5], acc[rr][6], acc[rr][7]);
        }
    }
}

// ---------------------------------------------------------------------------
// Launch: zero -> hist -> scanoff -> fill -> fused finalize.
// ---------------------------------------------------------------------------
extern "C" void kernel_launch(void* const* d_in, const int* in_sizes, int n_in,
                              void* d_out, int out_size) {
    const float* x  = (const float*)d_in[0];
    const int*   ei = (const int*)d_in[1];     // edge_index is int32 (JAX x64 off)
    const float* Wl = (const float*)d_in[2];
    const float* Wr = (const float*)d_in[3];
    float*       o  = (float*)d_out;

    const int E     = in_sizes[1] / 2;
    const int nodes = in_sizes[0] / D;
    const int scanb = (N_NODES + 255) / 256;

    static bool attr_set = false;
    if (!attr_set) {
        cudaFuncSetAttribute(finalize_kernel,
                             cudaFuncAttributeMaxDynamicSharedMemorySize,
                             SMEM_FIN_BYTES);
        attr_set = true;
    }

    zero_cnt_kernel<<<scanb, 256>>>();

    if ((E & 3) == 0) {
        int qb = (E / 4 + 255) / 256;
        hist4_kernel<<<qb, 256>>>(ei, E);
        scanoff_kernel<<<scanb, 256>>>();
        fill4_kernel<<<qb, 256>>>(ei, E);
    } else {
        int eb = (E + 255) / 256;
        hist_kernel<<<eb, 256>>>(ei, E);
        scanoff_kernel<<<scanb, 256>>>();
        fill_kernel<<<eb, 256>>>(ei, E);
    }

    finalize_kernel<<<(nodes + ROWS_BLK - 1) / ROWS_BLK, 256, SMEM_FIN_BYTES>>>(
        x, Wl, Wr, o, nodes);
}